// round 15
// baseline (speedup 1.0000x reference)
#include <cuda_runtime.h>
#include <cuda_fp16.h>

#define BQ    16384
#define DIN   1024
#define DOUT  1024
#define HDIM  2048
#define NE    8
#define NA    (BQ*2)
#define PADM  33792              /* segments padded to 128: 264 blocks of 128 */
#define MB    (PADM/128)         /* 264 */
#define KB1   (DIN/32)           /* 32 */
#define KB2   (HDIM/32)          /* 64 */
#define NT1   (HDIM/128)         /* 16 */
#define NT2   (DOUT/128)         /* 8  */

/* ---------------- scratch: fp16 fragment-blocked buffers ------------------- */
/* A-block (128 rows x 32 k) = 2048 uints: [ki(2)][mi(8)][lane(32)][4]         */
/* B-block (128 cols x 32 k) = 2048 uints: [ki(2)][ni(16)][lane(32)][2]        */
__device__ __align__(256) unsigned g_xh[(size_t)PADM * DIN / 2];
__device__ __align__(256) unsigned g_w1h[(size_t)NE * HDIM * DIN / 2];
__device__ __align__(256) unsigned g_w2h[(size_t)NE * DOUT * HDIM / 2];
__device__ __align__(256) unsigned g_hh[(size_t)PADM * HDIM / 2];
__device__ __align__(256) float    g_y[(size_t)PADM * DOUT];
__device__ int   g_tok[PADM];
__device__ float g_wgt[PADM];
__device__ int   g_slot[NA];
__device__ int   g_counts[NE];
__device__ int   g_cnt2[NE];
__device__ int   g_segbase[NE + 1];
__device__ int   g_tope[NA];
__device__ float g_topw[NA];
__device__ float g_probs_scratch[BQ * NE];

/* ---------------- helpers -------------------------------------------------- */
__device__ __forceinline__ void mma16816(float* c, const uint4 a, const uint2 b) {
    asm("mma.sync.aligned.m16n8k16.row.col.f32.f16.f16.f32 "
        "{%0,%1,%2,%3}, {%4,%5,%6,%7}, {%8,%9}, {%0,%1,%2,%3};"
        : "+f"(c[0]), "+f"(c[1]), "+f"(c[2]), "+f"(c[3])
        : "r"(a.x), "r"(a.y), "r"(a.z), "r"(a.w), "r"(b.x), "r"(b.y));
}
__device__ __forceinline__ unsigned pack2(float a, float b) {
    __half2 h = __floats2half2_rn(a, b);
    return *reinterpret_cast<unsigned*>(&h);
}

/* ---------------- init ------------------------------------------------------ */
__global__ void k_init() {
    int i = blockIdx.x * blockDim.x + threadIdx.x;
    if (i < NE) { g_counts[i] = 0; g_cnt2[i] = 0; }
    if (i < PADM) g_tok[i] = -1;
}

/* ---------------- router ---------------------------------------------------- */
__global__ void k_router(const float* __restrict__ x,
                         const float* __restrict__ rW,
                         const float* __restrict__ rb,
                         float* __restrict__ probs_out) {
    const int b = blockIdx.x;
    const int tid = threadIdx.x;
    const float* xr = x + (size_t)b * DIN;
    float acc[NE];
#pragma unroll
    for (int e = 0; e < NE; e++) acc[e] = 0.f;
    for (int k = tid; k < DIN; k += 128) {
        float xv = xr[k];
#pragma unroll
        for (int e = 0; e < NE; e++) acc[e] = fmaf(xv, rW[e * DIN + k], acc[e]);
    }
    __shared__ float red[NE][128];
#pragma unroll
    for (int e = 0; e < NE; e++) red[e][tid] = acc[e];
    __syncthreads();
    for (int s = 64; s > 0; s >>= 1) {
        if (tid < s) {
#pragma unroll
            for (int e = 0; e < NE; e++) red[e][tid] += red[e][tid + s];
        }
        __syncthreads();
    }
    if (tid == 0) {
        float lg[NE], mx = -1e30f;
#pragma unroll
        for (int e = 0; e < NE; e++) { lg[e] = red[e][0] + rb[e]; mx = fmaxf(mx, lg[e]); }
        float p[NE], s = 0.f;
#pragma unroll
        for (int e = 0; e < NE; e++) { p[e] = expf(lg[e] - mx); s += p[e]; }
        float inv = 1.f / s;
#pragma unroll
        for (int e = 0; e < NE; e++) { p[e] *= inv; probs_out[(size_t)b * NE + e] = p[e]; }
        int i0 = 0;
#pragma unroll
        for (int e = 1; e < NE; e++) if (p[e] > p[i0]) i0 = e;
        int i1 = (i0 == 0) ? 1 : 0;
#pragma unroll
        for (int e = 0; e < NE; e++) if (e != i0 && p[e] > p[i1]) i1 = e;
        float ws = p[i0] + p[i1];
        g_tope[2 * b]     = i0; g_topw[2 * b]     = p[i0] / ws;
        g_tope[2 * b + 1] = i1; g_topw[2 * b + 1] = p[i1] / ws;
        atomicAdd(&g_counts[i0], 1);
        atomicAdd(&g_counts[i1], 1);
    }
}

__global__ void k_prefix() {
    int base = 0;
    for (int e = 0; e < NE; e++) {
        g_segbase[e] = base;
        base += ((g_counts[e] + 127) >> 7) << 7;
    }
    g_segbase[NE] = base;
}
__global__ void k_scatter() {
    int a = blockIdx.x * 256 + threadIdx.x;
    if (a < NA) {
        int e = g_tope[a];
        int pos = g_segbase[e] + atomicAdd(&g_cnt2[e], 1);
        g_tok[pos] = a >> 1;
        g_wgt[pos] = g_topw[a];
        g_slot[a] = pos;
    }
}

/* ---------------- x: gather + fp16 convert into A-layout (128-row blocks) -- */
__global__ void k_xsplit(const float* __restrict__ x) {
    const int kb = blockIdx.x, mb = blockIdx.y;
    const int tid = threadIdx.x;                 /* 256 */
    const int lane = tid & 31, mi = tid >> 5;    /* mi 0..7 */
    const int g = lane >> 2, tig = lane & 3;
    const int row0 = mb * 128 + mi * 16 + g;
    const int t0 = g_tok[row0], t1 = g_tok[row0 + 8];
    const size_t blk = ((size_t)mb * KB1 + kb) * 2048;
#pragma unroll
    for (int ki = 0; ki < 2; ki++) {
        const int col = kb * 32 + ki * 16 + 2 * tig;
        float2 z = make_float2(0.f, 0.f);
        float2 v00 = z, v01 = z, v10 = z, v11 = z;
        if (t0 >= 0) {
            v00 = *(const float2*)&x[(size_t)t0 * DIN + col];
            v01 = *(const float2*)&x[(size_t)t0 * DIN + col + 8];
        }
        if (t1 >= 0) {
            v10 = *(const float2*)&x[(size_t)t1 * DIN + col];
            v11 = *(const float2*)&x[(size_t)t1 * DIN + col + 8];
        }
        uint4 H;
        H.x = pack2(v00.x, v00.y);
        H.y = pack2(v10.x, v10.y);
        H.z = pack2(v01.x, v01.y);
        H.w = pack2(v11.x, v11.y);
        *(uint4*)&g_xh[blk + ((size_t)(ki * 8 + mi) * 32 + lane) * 4] = H;
    }
}

/* ---------------- W1+W2 fp16 convert, single launch ------------------------- */
__global__ void k_wsplit(const float* __restrict__ W1f, const float* __restrict__ W2f,
                         unsigned* __restrict__ G1, unsigned* __restrict__ G2) {
    const int kb = blockIdx.x, nty = blockIdx.y, e = blockIdx.z;
    const bool is1 = (nty < NT1);
    if (is1 && kb >= KB1) return;
    const int nt = is1 ? nty : (nty - NT1);
    const int Kdim = is1 ? DIN : HDIM;
    const int NB = is1 ? NT1 : NT2;
    const float* W = is1 ? W1f : W2f;
    unsigned* Gh = is1 ? G1 : G2;

    const int tid = threadIdx.x;                 /* 512 */
    const int lane = tid & 31, ni = tid >> 5;
    const int g = lane >> 2, tig = lane & 3;
    const size_t nrow = (size_t)e * (NB * 128) + nt * 128 + ni * 8 + g;
    const float* src = W + nrow * Kdim + kb * 32;
    const size_t blk = (((size_t)e * NB + nt) * (Kdim / 32) + kb) * 2048;
#pragma unroll
    for (int ki = 0; ki < 2; ki++) {
        const int k0 = ki * 16 + 2 * tig;
        float2 w0 = *(const float2*)&src[k0];
        float2 w1 = *(const float2*)&src[k0 + 8];
        uint2 H;
        H.x = pack2(w0.x, w0.y);
        H.y = pack2(w1.x, w1.y);
        *(uint2*)&Gh[blk + ((size_t)(ki * 16 + ni) * 32 + lane) * 2] = H;
    }
}

/* ---------------- register prefetch: A 4xLDG.128, B 8xLDG.64 ---------------- */
__device__ __forceinline__ void ldg_a4(uint4* ah, const unsigned* p) {
#pragma unroll
    for (int i = 0; i < 4; i++)
        ah[i] = __ldg((const uint4*)(p + i * 128));
}
__device__ __forceinline__ void ldg_b8(uint2* bh, const unsigned* p) {
#pragma unroll
    for (int j = 0; j < 8; j++)
        bh[j] = __ldg((const uint2*)(p + j * 64));
}

/* ---------------- GEMM mainloop: all-register, no smem, no barriers --------- */
/* half-kblock h (16 K-values): A at Ag + h*1024, B at Bg + h*1024.            */
__device__ __forceinline__ void gemm_loop(
    const unsigned* __restrict__ Ah, const unsigned* __restrict__ Bh,
    size_t ablk0, size_t bblk0, int KB,
    float acc[4][8][4], int tid)
{
    const int lane = tid & 31, wid = tid >> 5;
    const int wm = wid >> 1, wn = wid & 1;     /* 2 m-warps x 2 n-warps, 64x64 */
    const unsigned* Ag = Ah + ablk0 * 2048 + (size_t)(wm * 4) * 128 + lane * 4;
    const unsigned* Bg = Bh + bblk0 * 2048 + (size_t)(wn * 8) * 64 + lane * 2;

    uint4 ah0[4], ah1[4];
    uint2 bh0[8], bh1[8];
    ldg_a4(ah0, Ag);
    ldg_b8(bh0, Bg);
    ldg_a4(ah1, Ag + 1024);
    ldg_b8(bh1, Bg + 1024);

    for (int it = 0; it < KB; it++) {          /* it = kblock = 2 half-kblocks */
        const bool more = (it + 1 < KB);
        const size_t off = (size_t)(2 * it + 2) * 1024;
#pragma unroll
        for (int i = 0; i < 4; i++)
#pragma unroll
            for (int j = 0; j < 8; j++) mma16816(acc[i][j], ah0[i], bh0[j]);
        if (more) {
            ldg_a4(ah0, Ag + off);
            ldg_b8(bh0, Bg + off);
        }
#pragma unroll
        for (int i = 0; i < 4; i++)
#pragma unroll
            for (int j = 0; j < 8; j++) mma16816(acc[i][j], ah1[i], bh1[j]);
        if (more) {
            ldg_a4(ah1, Ag + off + 1024);
            ldg_b8(bh1, Bg + off + 1024);
        }
    }
}

__device__ __forceinline__ int resolve_expert(int p0) {
    int e = -1;
    if (p0 < g_segbase[NE]) {
#pragma unroll
        for (int i = NE - 1; i >= 0; i--)
            if (p0 >= g_segbase[i]) { e = i; break; }
    }
    return e;
}

/* ---------------- GEMM1: h = relu(X W1^T + b1) -> fp16 A-layout ------------- */
__global__ __launch_bounds__(128, 2)
void k_gemm1(const float* __restrict__ b1) {
    __shared__ int s_e;
    const int tid = threadIdx.x;
    const int nt = blockIdx.x, mt = blockIdx.y;

    if (tid == 0) s_e = resolve_expert(mt * 128);
    __syncthreads();
    const int e = s_e;
    if (e < 0) return;

    float acc[4][8][4];
#pragma unroll
    for (int i = 0; i < 4; i++)
#pragma unroll
        for (int j = 0; j < 8; j++)
#pragma unroll
            for (int c = 0; c < 4; c++) acc[i][j][c] = 0.f;

    gemm_loop(g_xh, g_w1h,
              (size_t)mt * KB1, ((size_t)e * NT1 + nt) * KB1, KB1, acc, tid);

    /* epilogue: bias+relu, fp16 convert, write h in A-layout (C-frag == A-frag) */
    const int lane = tid & 31, wid = tid >> 5;
    const int wm = wid >> 1, wn = wid & 1;
    const int tig = lane & 3;
    const float* bias = b1 + (size_t)e * HDIM + nt * 128 + wn * 64 + 2 * tig;
#pragma unroll
    for (int mi = 0; mi < 4; mi++) {
        const int mi8 = wm * 4 + mi;            /* 16-row group within 128 */
#pragma unroll
        for (int jp = 0; jp < 4; jp++) {
            float2 b0 = *(const float2*)(bias + (2 * jp) * 8);
            float2 b1v = *(const float2*)(bias + (2 * jp + 1) * 8);
            const float* c0 = acc[mi][2 * jp];
            const float* c1 = acc[mi][2 * jp + 1];
            uint4 H;
            H.x = pack2(fmaxf(c0[0] + b0.x, 0.f),  fmaxf(c0[1] + b0.y, 0.f));
            H.y = pack2(fmaxf(c0[2] + b0.x, 0.f),  fmaxf(c0[3] + b0.y, 0.f));
            H.z = pack2(fmaxf(c1[0] + b1v.x, 0.f), fmaxf(c1[1] + b1v.y, 0.f));
            H.w = pack2(fmaxf(c1[2] + b1v.x, 0.f), fmaxf(c1[3] + b1v.y, 0.f));
            const int hcol0 = nt * 128 + wn * 64 + jp * 16;
            const size_t base = ((size_t)mt * KB2 + (hcol0 >> 5)) * 2048
                + ((size_t)(((hcol0 >> 4) & 1) * 8 + mi8) * 32 + lane) * 4;
            *(uint4*)&g_hh[base] = H;
        }
    }
}

/* ---------------- GEMM2: y_slot = w * (h W2^T + b2), plain stores ----------- */
__global__ __launch_bounds__(128, 2)
void k_gemm2(const float* __restrict__ b2) {
    __shared__ int s_e;
    __shared__ int stok[128];
    __shared__ float swgt[128];
    const int tid = threadIdx.x;
    const int nt = blockIdx.x, mt = blockIdx.y;

    if (tid == 0) s_e = resolve_expert(mt * 128);
    __syncthreads();
    const int e = s_e;
    if (e < 0) return;

    stok[tid] = g_tok[mt * 128 + tid];
    swgt[tid] = g_wgt[mt * 128 + tid];
    __syncthreads();           /* mainloop has no barriers now */

    float acc[4][8][4];
#pragma unroll
    for (int i = 0; i < 4; i++)
#pragma unroll
        for (int j = 0; j < 8; j++)
#pragma unroll
            for (int c = 0; c < 4; c++) acc[i][j][c] = 0.f;

    gemm_loop(g_hh, g_w2h,
              (size_t)mt * KB2, ((size_t)e * NT2 + nt) * KB2, KB2, acc, tid);

    const int lane = tid & 31, wid = tid >> 5;
    const int wm = wid >> 1, wn = wid & 1;
    const int g = lane >> 2, tig = lane & 3;
#pragma unroll
    for (int mi = 0; mi < 4; mi++) {
        const int r0 = wm * 64 + mi * 16 + g;
        const int t0 = stok[r0], t1 = stok[r0 + 8];
        const float w0 = swgt[r0], w1 = swgt[r0 + 8];
        float* y0 = g_y + (size_t)(mt * 128 + r0) * DOUT;
        float* y1 = y0 + (size_t)8 * DOUT;
#pragma unroll
        for (int j = 0; j < 8; j++) {
            const int col = nt * 128 + wn * 64 + j * 8 + 2 * tig;
            float2 bb = *(const float2*)&b2[(size_t)e * DOUT + col];
            if (t0 >= 0) {
                float2 v = make_float2(w0 * (acc[mi][j][0] + bb.x),
                                       w0 * (acc[mi][j][1] + bb.y));
                *(float2*)(y0 + col) = v;
            }
            if (t1 >= 0) {
                float2 v = make_float2(w1 * (acc[mi][j][2] + bb.x),
                                       w1 * (acc[mi][j][3] + bb.y));
                *(float2*)(y1 + col) = v;
            }
        }
    }
}

/* ---------------- combine: out[t] = y[slot0] + y[slot1] --------------------- */
__global__ void k_combine(float* __restrict__ out) {
    const int t = blockIdx.x;
    const int c = threadIdx.x;
    const int s0 = g_slot[2 * t], s1 = g_slot[2 * t + 1];
    const float4 a = ((const float4*)(g_y + (size_t)s0 * DOUT))[c];
    const float4 b = ((const float4*)(g_y + (size_t)s1 * DOUT))[c];
    ((float4*)(out + (size_t)t * DOUT))[c] =
        make_float4(a.x + b.x, a.y + b.y, a.z + b.z, a.w + b.w);
}

/* ---------------- launch ----------------------------------------------------- */
extern "C" void kernel_launch(void* const* d_in, const int* in_sizes, int n_in,
                              void* d_out, int out_size) {
    const float* x  = (const float*)d_in[0];
    const float* rW = (const float*)d_in[1];
    const float* rb = (const float*)d_in[2];
    const float* W1 = (const float*)d_in[3];
    const float* b1 = (const float*)d_in[4];
    const float* W2 = (const float*)d_in[5];
    const float* b2 = (const float*)d_in[6];
    float* out = (float*)d_out;

    float* probs;
    if (out_size >= (int)(BQ * DOUT + BQ * NE)) {
        probs = out + (size_t)BQ * DOUT;
    } else {
        void* p = nullptr;
        cudaGetSymbolAddress(&p, g_probs_scratch);
        probs = (float*)p;
    }

    /* resolve DEVICE addresses for scratch passed as kernel args (ATS trap!) */
    void *p_w1h = nullptr, *p_w2h = nullptr;
    cudaGetSymbolAddress(&p_w1h, g_w1h);
    cudaGetSymbolAddress(&p_w2h, g_w2h);

    k_init<<<(PADM + 255) / 256, 256>>>();
    k_router<<<BQ, 128>>>(x, rW, rb, probs);
    k_prefix<<<1, 1>>>();
    k_scatter<<<NA / 256, 256>>>();
    k_xsplit<<<dim3(KB1, MB), 256>>>(x);
    k_wsplit<<<dim3(KB2, NT1 + NT2, NE), 512>>>(W1, W2,
                                                (unsigned*)p_w1h, (unsigned*)p_w2h);
    k_gemm1<<<dim3(NT1, MB), 128>>>(b1);
    k_gemm2<<<dim3(NT2, MB), 128>>>(b2);
    k_combine<<<BQ, 256>>>(out);
    (void)in_sizes; (void)n_in;
}

// round 16
// speedup vs baseline: 1.0882x; 1.0882x over previous
#include <cuda_runtime.h>
#include <cuda_fp16.h>

#define BQ    16384
#define DIN   1024
#define DOUT  1024
#define HDIM  2048
#define NE    8
#define NA    (BQ*2)
#define PADM  33792              /* segments padded to 128: 264 blocks of 128 */
#define MB    (PADM/128)         /* 264 */
#define KB1   (DIN/32)           /* 32 */
#define KB2   (HDIM/32)          /* 64 */
#define NT1   (HDIM/128)         /* 16 */
#define NT2   (DOUT/128)         /* 8  */
#define STAGE_UINTS 4096         /* 16KB: A only, 2 kblocks */
#define NSTAGE 4
#define DSMEM_BYTES (NSTAGE*STAGE_UINTS*4)   /* 65536 -> 2 CTAs/SM */

/* ---------------- scratch: fp16 fragment-blocked buffers ------------------- */
/* A-block (128 rows x 32 k) = 2048 uints: [ki(2)][mi(8)][lane(32)][4]         */
/* B-block (128 cols x 32 k) = 2048 uints: [ki(2)][ni(16)][lane(32)][2]        */
__device__ __align__(256) unsigned g_xh[(size_t)PADM * DIN / 2];
__device__ __align__(256) unsigned g_w1h[(size_t)NE * HDIM * DIN / 2];
__device__ __align__(256) unsigned g_w2h[(size_t)NE * DOUT * HDIM / 2];
__device__ __align__(256) unsigned g_hh[(size_t)PADM * HDIM / 2];
__device__ __align__(256) unsigned g_yh[(size_t)PADM * DOUT / 2];  /* fp16 y */
__device__ int   g_tok[PADM];
__device__ float g_wgt[PADM];
__device__ int   g_slot[NA];
__device__ int   g_counts[NE];
__device__ int   g_cnt2[NE];
__device__ int   g_segbase[NE + 1];
__device__ int   g_tope[NA];
__device__ float g_topw[NA];
__device__ float g_probs_scratch[BQ * NE];

/* ---------------- helpers -------------------------------------------------- */
__device__ __forceinline__ unsigned smem_u32(const void* p) {
    unsigned a;
    asm("{ .reg .u64 t; cvta.to.shared.u64 t, %1; cvt.u32.u64 %0, t; }" : "=r"(a) : "l"(p));
    return a;
}
#define CP16(dst, src) \
    asm volatile("cp.async.cg.shared.global [%0], [%1], 16;" :: "r"(dst), "l"(src) : "memory")
#define CP_COMMIT() asm volatile("cp.async.commit_group;" ::: "memory")

__device__ __forceinline__ void mma16816(float* c, const uint4 a, const uint2 b) {
    asm("mma.sync.aligned.m16n8k16.row.col.f32.f16.f16.f32 "
        "{%0,%1,%2,%3}, {%4,%5,%6,%7}, {%8,%9}, {%0,%1,%2,%3};"
        : "+f"(c[0]), "+f"(c[1]), "+f"(c[2]), "+f"(c[3])
        : "r"(a.x), "r"(a.y), "r"(a.z), "r"(a.w), "r"(b.x), "r"(b.y));
}
__device__ __forceinline__ unsigned pack2(float a, float b) {
    __half2 h = __floats2half2_rn(a, b);
    return *reinterpret_cast<unsigned*>(&h);
}

/* ---------------- init ------------------------------------------------------ */
__global__ void k_init() {
    int i = blockIdx.x * blockDim.x + threadIdx.x;
    if (i < NE) { g_counts[i] = 0; g_cnt2[i] = 0; }
    if (i < PADM) g_tok[i] = -1;
}

/* ---------------- router ---------------------------------------------------- */
__global__ void k_router(const float* __restrict__ x,
                         const float* __restrict__ rW,
                         const float* __restrict__ rb,
                         float* __restrict__ probs_out) {
    const int b = blockIdx.x;
    const int tid = threadIdx.x;
    const float* xr = x + (size_t)b * DIN;
    float acc[NE];
#pragma unroll
    for (int e = 0; e < NE; e++) acc[e] = 0.f;
    for (int k = tid; k < DIN; k += 128) {
        float xv = xr[k];
#pragma unroll
        for (int e = 0; e < NE; e++) acc[e] = fmaf(xv, rW[e * DIN + k], acc[e]);
    }
    __shared__ float red[NE][128];
#pragma unroll
    for (int e = 0; e < NE; e++) red[e][tid] = acc[e];
    __syncthreads();
    for (int s = 64; s > 0; s >>= 1) {
        if (tid < s) {
#pragma unroll
            for (int e = 0; e < NE; e++) red[e][tid] += red[e][tid + s];
        }
        __syncthreads();
    }
    if (tid == 0) {
        float lg[NE], mx = -1e30f;
#pragma unroll
        for (int e = 0; e < NE; e++) { lg[e] = red[e][0] + rb[e]; mx = fmaxf(mx, lg[e]); }
        float p[NE], s = 0.f;
#pragma unroll
        for (int e = 0; e < NE; e++) { p[e] = expf(lg[e] - mx); s += p[e]; }
        float inv = 1.f / s;
#pragma unroll
        for (int e = 0; e < NE; e++) { p[e] *= inv; probs_out[(size_t)b * NE + e] = p[e]; }
        int i0 = 0;
#pragma unroll
        for (int e = 1; e < NE; e++) if (p[e] > p[i0]) i0 = e;
        int i1 = (i0 == 0) ? 1 : 0;
#pragma unroll
        for (int e = 0; e < NE; e++) if (e != i0 && p[e] > p[i1]) i1 = e;
        float ws = p[i0] + p[i1];
        g_tope[2 * b]     = i0; g_topw[2 * b]     = p[i0] / ws;
        g_tope[2 * b + 1] = i1; g_topw[2 * b + 1] = p[i1] / ws;
        atomicAdd(&g_counts[i0], 1);
        atomicAdd(&g_counts[i1], 1);
    }
}

__global__ void k_prefix() {
    int base = 0;
    for (int e = 0; e < NE; e++) {
        g_segbase[e] = base;
        base += ((g_counts[e] + 127) >> 7) << 7;
    }
    g_segbase[NE] = base;
}
__global__ void k_scatter() {
    int a = blockIdx.x * 256 + threadIdx.x;
    if (a < NA) {
        int e = g_tope[a];
        int pos = g_segbase[e] + atomicAdd(&g_cnt2[e], 1);
        g_tok[pos] = a >> 1;
        g_wgt[pos] = g_topw[a];
        g_slot[a] = pos;
    }
}

/* ---------------- x: gather + fp16 convert into A-layout (128-row blocks) -- */
__global__ void k_xsplit(const float* __restrict__ x) {
    const int kb = blockIdx.x, mb = blockIdx.y;
    const int tid = threadIdx.x;                 /* 256 */
    const int lane = tid & 31, mi = tid >> 5;    /* mi 0..7 */
    const int g = lane >> 2, tig = lane & 3;
    const int row0 = mb * 128 + mi * 16 + g;
    const int t0 = g_tok[row0], t1 = g_tok[row0 + 8];
    const size_t blk = ((size_t)mb * KB1 + kb) * 2048;
#pragma unroll
    for (int ki = 0; ki < 2; ki++) {
        const int col = kb * 32 + ki * 16 + 2 * tig;
        float2 z = make_float2(0.f, 0.f);
        float2 v00 = z, v01 = z, v10 = z, v11 = z;
        if (t0 >= 0) {
            v00 = *(const float2*)&x[(size_t)t0 * DIN + col];
            v01 = *(const float2*)&x[(size_t)t0 * DIN + col + 8];
        }
        if (t1 >= 0) {
            v10 = *(const float2*)&x[(size_t)t1 * DIN + col];
            v11 = *(const float2*)&x[(size_t)t1 * DIN + col + 8];
        }
        uint4 H;
        H.x = pack2(v00.x, v00.y);
        H.y = pack2(v10.x, v10.y);
        H.z = pack2(v01.x, v01.y);
        H.w = pack2(v11.x, v11.y);
        *(uint4*)&g_xh[blk + ((size_t)(ki * 8 + mi) * 32 + lane) * 4] = H;
    }
}

/* ---------------- W1+W2 fp16 convert, single launch ------------------------- */
__global__ void k_wsplit(const float* __restrict__ W1f, const float* __restrict__ W2f,
                         unsigned* __restrict__ G1, unsigned* __restrict__ G2) {
    const int kb = blockIdx.x, nty = blockIdx.y, e = blockIdx.z;
    const bool is1 = (nty < NT1);
    if (is1 && kb >= KB1) return;
    const int nt = is1 ? nty : (nty - NT1);
    const int Kdim = is1 ? DIN : HDIM;
    const int NB = is1 ? NT1 : NT2;
    const float* W = is1 ? W1f : W2f;
    unsigned* Gh = is1 ? G1 : G2;

    const int tid = threadIdx.x;                 /* 512 */
    const int lane = tid & 31, ni = tid >> 5;
    const int g = lane >> 2, tig = lane & 3;
    const size_t nrow = (size_t)e * (NB * 128) + nt * 128 + ni * 8 + g;
    const float* src = W + nrow * Kdim + kb * 32;
    const size_t blk = (((size_t)e * NB + nt) * (Kdim / 32) + kb) * 2048;
#pragma unroll
    for (int ki = 0; ki < 2; ki++) {
        const int k0 = ki * 16 + 2 * tig;
        float2 w0 = *(const float2*)&src[k0];
        float2 w1 = *(const float2*)&src[k0 + 8];
        uint2 H;
        H.x = pack2(w0.x, w0.y);
        H.y = pack2(w1.x, w1.y);
        *(uint2*)&Gh[blk + ((size_t)(ki * 16 + ni) * 32 + lane) * 2] = H;
    }
}

/* ---------------- stage loader: 16KB A-only (2 kblocks), 128 threads -------- */
__device__ __forceinline__ void stage_load(
    unsigned* smbuf, int st, const unsigned* __restrict__ Ah,
    size_t ablk, int tid)
{
    unsigned d = smem_u32(smbuf + st * STAGE_UINTS) + tid * 16;
    const unsigned* a = Ah + ablk * 2048 + tid * 4;
#pragma unroll
    for (int i = 0; i < 8; i++) CP16(d + i * 2048, a + i * 512);
    CP_COMMIT();
}

/* B-fragment register prefetch: 8 x LDG.64 per half-kblock per warp ---------- */
__device__ __forceinline__ void ldg_b8(uint2* bh, const unsigned* p) {
#pragma unroll
    for (int j = 0; j < 8; j++)
        bh[j] = __ldg((const uint2*)(p + j * 64));
}

/* ---------------- GEMM mainloop (CTA 128x128, 4 warps 64x64, 4 stages) ----- */
/* A via 4-stage cp.async smem pipeline; B via double-buffered register LDG.   */
__device__ __forceinline__ void gemm_loop(
    unsigned* smbuf,
    const unsigned* __restrict__ Ah, const unsigned* __restrict__ Bh,
    size_t ablk0, size_t bblk0, int KB,
    float acc[4][8][4], int tid)
{
    const int lane = tid & 31, wid = tid >> 5;
    const int wm = wid >> 1, wn = wid & 1;     /* 2 m-warps x 2 n-warps, 64x64 */
    const int KH = KB >> 1;
    const int HTOT = 2 * KB;                   /* half-kblocks total */
    const unsigned* Bg = Bh + bblk0 * 2048 + (size_t)(wn * 8) * 64 + lane * 2;

    uint2 bh0[8], bh1[8];
    ldg_b8(bh0, Bg);               /* h = 0 */
    ldg_b8(bh1, Bg + 1024);        /* h = 1 */

    stage_load(smbuf, 0, Ah, ablk0,     tid);
    stage_load(smbuf, 1, Ah, ablk0 + 2, tid);
    stage_load(smbuf, 2, Ah, ablk0 + 4, tid);

    int st = 0;
    for (int it = 0; it < KH; it++) {
        if (it + 2 < KH) {
            asm volatile("cp.async.wait_group 2;" ::: "memory");
        } else if (it + 1 < KH) {
            asm volatile("cp.async.wait_group 1;" ::: "memory");
        } else {
            asm volatile("cp.async.wait_group 0;" ::: "memory");
        }
        __syncthreads();
        const unsigned* base = smbuf + st * STAGE_UINTS;
#pragma unroll
        for (int hh = 0; hh < 4; hh++) {
            const int kk = hh >> 1, ki = hh & 1;
            const unsigned* sA = base + kk * 2048;
            const unsigned* pa = sA + ((ki * 8 + wm * 4) * 32 + lane) * 4;
            uint4 ah[4];
#pragma unroll
            for (int i = 0; i < 4; i++) ah[i] = *(const uint4*)(pa + i * 128);
            uint2* bc = (hh & 1) ? bh1 : bh0;
#pragma unroll
            for (int i = 0; i < 4; i++)
#pragma unroll
                for (int j = 0; j < 8; j++) mma16816(acc[i][j], ah[i], bc[j]);
            const int h = 4 * it + hh;
            if (h + 2 < HTOT)                   /* refill freed buffer, h+2 */
                ldg_b8(bc, Bg + (size_t)(h + 2) * 1024);
        }
        if (it + 3 < KH) {
            int nst = st + 3; if (nst >= NSTAGE) nst -= NSTAGE;
            stage_load(smbuf, nst, Ah, ablk0 + 2 * (it + 3), tid);
        }
        if (++st == NSTAGE) st = 0;
    }
}

__device__ __forceinline__ int resolve_expert(int p0) {
    int e = -1;
    if (p0 < g_segbase[NE]) {
#pragma unroll
        for (int i = NE - 1; i >= 0; i--)
            if (p0 >= g_segbase[i]) { e = i; break; }
    }
    return e;
}

/* ---------------- GEMM1: h = relu(X W1^T + b1) -> fp16 A-layout ------------- */
__global__ __launch_bounds__(128, 2)
void k_gemm1(const float* __restrict__ b1) {
    __shared__ int s_e;
    extern __shared__ unsigned smbuf[];
    const int tid = threadIdx.x;
    const int nt = blockIdx.x, mt = blockIdx.y;

    if (tid == 0) s_e = resolve_expert(mt * 128);
    __syncthreads();
    const int e = s_e;
    if (e < 0) return;

    float acc[4][8][4];
#pragma unroll
    for (int i = 0; i < 4; i++)
#pragma unroll
        for (int j = 0; j < 8; j++)
#pragma unroll
            for (int c = 0; c < 4; c++) acc[i][j][c] = 0.f;

    gemm_loop(smbuf, g_xh, g_w1h,
              (size_t)mt * KB1, ((size_t)e * NT1 + nt) * KB1, KB1, acc, tid);

    /* epilogue: bias+relu, fp16 convert, write h in A-layout (C-frag == A-frag) */
    const int lane = tid & 31, wid = tid >> 5;
    const int wm = wid >> 1, wn = wid & 1;
    const int tig = lane & 3;
    const float* bias = b1 + (size_t)e * HDIM + nt * 128 + wn * 64 + 2 * tig;
#pragma unroll
    for (int mi = 0; mi < 4; mi++) {
        const int mi8 = wm * 4 + mi;            /* 16-row group within 128 */
#pragma unroll
        for (int jp = 0; jp < 4; jp++) {
            float2 b0 = *(const float2*)(bias + (2 * jp) * 8);
            float2 b1v = *(const float2*)(bias + (2 * jp + 1) * 8);
            const float* c0 = acc[mi][2 * jp];
            const float* c1 = acc[mi][2 * jp + 1];
            uint4 H;
            H.x = pack2(fmaxf(c0[0] + b0.x, 0.f),  fmaxf(c0[1] + b0.y, 0.f));
            H.y = pack2(fmaxf(c0[2] + b0.x, 0.f),  fmaxf(c0[3] + b0.y, 0.f));
            H.z = pack2(fmaxf(c1[0] + b1v.x, 0.f), fmaxf(c1[1] + b1v.y, 0.f));
            H.w = pack2(fmaxf(c1[2] + b1v.x, 0.f), fmaxf(c1[3] + b1v.y, 0.f));
            const int hcol0 = nt * 128 + wn * 64 + jp * 16;
            const size_t base = ((size_t)mt * KB2 + (hcol0 >> 5)) * 2048
                + ((size_t)(((hcol0 >> 4) & 1) * 8 + mi8) * 32 + lane) * 4;
            *(uint4*)&g_hh[base] = H;
        }
    }
}

/* ---------------- GEMM2: y_slot = w * (h W2^T + b2), fp16 stores ------------ */
__global__ __launch_bounds__(128, 2)
void k_gemm2(const float* __restrict__ b2) {
    __shared__ int s_e;
    __shared__ int stok[128];
    __shared__ float swgt[128];
    extern __shared__ unsigned smbuf[];
    const int tid = threadIdx.x;
    const int nt = blockIdx.x, mt = blockIdx.y;

    if (tid == 0) s_e = resolve_expert(mt * 128);
    __syncthreads();
    const int e = s_e;
    if (e < 0) return;

    stok[tid] = g_tok[mt * 128 + tid];
    swgt[tid] = g_wgt[mt * 128 + tid];

    float acc[4][8][4];
#pragma unroll
    for (int i = 0; i < 4; i++)
#pragma unroll
        for (int j = 0; j < 8; j++)
#pragma unroll
            for (int c = 0; c < 4; c++) acc[i][j][c] = 0.f;

    gemm_loop(smbuf, g_hh, g_w2h,
              (size_t)mt * KB2, ((size_t)e * NT2 + nt) * KB2, KB2, acc, tid);

    const int lane = tid & 31, wid = tid >> 5;
    const int wm = wid >> 1, wn = wid & 1;
    const int g = lane >> 2, tig = lane & 3;
#pragma unroll
    for (int mi = 0; mi < 4; mi++) {
        const int r0 = wm * 64 + mi * 16 + g;
        const int t0 = stok[r0], t1 = stok[r0 + 8];
        const float w0 = swgt[r0], w1 = swgt[r0 + 8];
        unsigned* y0 = g_yh + (size_t)(mt * 128 + r0) * (DOUT / 2);
        unsigned* y1 = y0 + (size_t)8 * (DOUT / 2);
#pragma unroll
        for (int j = 0; j < 8; j++) {
            const int col = nt * 128 + wn * 64 + j * 8 + 2 * tig;
            float2 bb = *(const float2*)&b2[(size_t)e * DOUT + col];
            if (t0 >= 0)
                y0[col >> 1] = pack2(w0 * (acc[mi][j][0] + bb.x),
                                     w0 * (acc[mi][j][1] + bb.y));
            if (t1 >= 0)
                y1[col >> 1] = pack2(w1 * (acc[mi][j][2] + bb.x),
                                     w1 * (acc[mi][j][3] + bb.y));
        }
    }
}

/* ---------------- combine: out[t] = y[slot0] + y[slot1] (fp32 sum) ---------- */
__global__ void k_combine(float* __restrict__ out) {
    const int t = blockIdx.x;
    const int c = threadIdx.x;               /* 256 threads x 4 floats = 1024 */
    const int s0 = g_slot[2 * t], s1 = g_slot[2 * t + 1];
    const uint2 a = ((const uint2*)(g_yh + (size_t)s0 * (DOUT / 2)))[c];
    const uint2 b = ((const uint2*)(g_yh + (size_t)s1 * (DOUT / 2)))[c];
    float2 a0 = __half22float2(*(const __half2*)&a.x);
    float2 a1 = __half22float2(*(const __half2*)&a.y);
    float2 b0 = __half22float2(*(const __half2*)&b.x);
    float2 b1 = __half22float2(*(const __half2*)&b.y);
    ((float4*)(out + (size_t)t * DOUT))[c] =
        make_float4(a0.x + b0.x, a0.y + b0.y, a1.x + b1.x, a1.y + b1.y);
}

/* ---------------- launch ----------------------------------------------------- */
extern "C" void kernel_launch(void* const* d_in, const int* in_sizes, int n_in,
                              void* d_out, int out_size) {
    const float* x  = (const float*)d_in[0];
    const float* rW = (const float*)d_in[1];
    const float* rb = (const float*)d_in[2];
    const float* W1 = (const float*)d_in[3];
    const float* b1 = (const float*)d_in[4];
    const float* W2 = (const float*)d_in[5];
    const float* b2 = (const float*)d_in[6];
    float* out = (float*)d_out;

    float* probs;
    if (out_size >= (int)(BQ * DOUT + BQ * NE)) {
        probs = out + (size_t)BQ * DOUT;
    } else {
        void* p = nullptr;
        cudaGetSymbolAddress(&p, g_probs_scratch);
        probs = (float*)p;
    }

    /* resolve DEVICE addresses for scratch passed as kernel args (ATS trap!) */
    void *p_w1h = nullptr, *p_w2h = nullptr;
    cudaGetSymbolAddress(&p_w1h, g_w1h);
    cudaGetSymbolAddress(&p_w2h, g_w2h);

    cudaFuncSetAttribute(k_gemm1, cudaFuncAttributeMaxDynamicSharedMemorySize, DSMEM_BYTES);
    cudaFuncSetAttribute(k_gemm2, cudaFuncAttributeMaxDynamicSharedMemorySize, DSMEM_BYTES);

    k_init<<<(PADM + 255) / 256, 256>>>();
    k_router<<<BQ, 128>>>(x, rW, rb, probs);
    k_prefix<<<1, 1>>>();
    k_scatter<<<NA / 256, 256>>>();
    k_xsplit<<<dim3(KB1, MB), 256>>>(x);
    k_wsplit<<<dim3(KB2, NT1 + NT2, NE), 512>>>(W1, W2,
                                                (unsigned*)p_w1h, (unsigned*)p_w2h);
    k_gemm1<<<dim3(NT1, MB), 128, DSMEM_BYTES>>>(b1);
    k_gemm2<<<dim3(NT2, MB), 128, DSMEM_BYTES>>>(b2);
    k_combine<<<BQ, 256>>>(out);
    (void)in_sizes; (void)n_in;
}